// round 2
// baseline (speedup 1.0000x reference)
#include <cuda_runtime.h>
#include <math.h>

#define B 32
#define T 512
#define HID 512
#define VOCAB 4096
#define M_TOT (T * B)          // 16384 output rows

// All hidden states across time: [T][B][HID]  (row index t*B+b matches output layout)
__device__ float g_Hall[T * B * HID];   // 32 MB static scratch (allowed)

// ---------------------------------------------------------------------------
// Recurrence step: H_t = tanh(W_xh[x_t] + H_{t-1} @ W_hh + b_h)
// grid: (8 j-tiles of 64, 8 b-tiles of 4), 256 threads = 64 j-lanes x 4 k-groups
// ---------------------------------------------------------------------------
__global__ void __launch_bounds__(256) rnn_step(
    const int* __restrict__ X,        // (B, T)
    const float* __restrict__ state,  // (B, HID)
    const float* __restrict__ W_xh,   // (VOCAB, HID)
    const float* __restrict__ W_hh,   // (HID, HID)
    const float* __restrict__ b_h,    // (HID)
    int t)
{
    __shared__ float sH[4][HID];            // 4 batch rows of H_{t-1}
    __shared__ float sPart[4][64][4];       // [kgroup][j-lane][b-sub]

    const int tid = threadIdx.x;
    const int jl  = tid & 63;               // 0..63
    const int kg  = tid >> 6;               // 0..3
    const int j   = blockIdx.x * 64 + jl;   // hidden index
    const int b0  = blockIdx.y * 4;         // batch tile base

    const float* Hprev = (t == 0) ? state : (g_Hall + (size_t)(t - 1) * B * HID);

    // cooperative load of 4 H rows (coalesced)
    for (int i = tid; i < 4 * HID; i += 256) {
        int bi = i >> 9;         // i / HID
        int kk = i & (HID - 1);  // i % HID
        sH[bi][kk] = Hprev[(b0 + bi) * HID + kk];
    }
    __syncthreads();

    float acc0 = 0.f, acc1 = 0.f, acc2 = 0.f, acc3 = 0.f;
    const int kbase = kg * 128;
    #pragma unroll 4
    for (int k = 0; k < 128; k++) {
        const float w = __ldg(&W_hh[(kbase + k) * HID + j]);
        acc0 += sH[0][kbase + k] * w;
        acc1 += sH[1][kbase + k] * w;
        acc2 += sH[2][kbase + k] * w;
        acc3 += sH[3][kbase + k] * w;
    }
    sPart[kg][jl][0] = acc0;
    sPart[kg][jl][1] = acc1;
    sPart[kg][jl][2] = acc2;
    sPart[kg][jl][3] = acc3;
    __syncthreads();

    // thread (jl, kg) finalizes batch row bi = kg for hidden index j
    const int bi = kg;
    float s = sPart[0][jl][bi] + sPart[1][jl][bi] + sPart[2][jl][bi] + sPart[3][jl][bi];
    const int b   = b0 + bi;
    const int tok = X[b * T + t];                  // X is (B, T); x_t[b] = X[b][t]
    s += __ldg(&W_xh[(size_t)tok * HID + j]) + __ldg(&b_h[j]);
    g_Hall[(size_t)t * B * HID + b * HID + j] = tanhf(s);
}

// ---------------------------------------------------------------------------
// Projection GEMM: C[M_TOT, VOCAB] = g_Hall[M_TOT, HID] @ W_hq[HID, VOCAB] + b_q
// 128x128 block tile, BK=8, 256 threads, 8x8 per-thread register tile
// ---------------------------------------------------------------------------
__global__ void __launch_bounds__(256) proj_gemm(
    const float* __restrict__ Wq,     // (HID, VOCAB)
    const float* __restrict__ bq,     // (VOCAB)
    float* __restrict__ C)            // (M_TOT, VOCAB)
{
    __shared__ float As[8][128];
    __shared__ float Bs[8][132];      // +4 pad, keeps 16B alignment per row

    const int tid = threadIdx.x;
    const int bm = blockIdx.y * 128;
    const int bn = blockIdx.x * 128;
    const int tx = tid & 15;          // n sub-tile
    const int ty = tid >> 4;          // m sub-tile

    float acc[8][8];
    #pragma unroll
    for (int i = 0; i < 8; i++)
        #pragma unroll
        for (int jj = 0; jj < 8; jj++) acc[i][jj] = 0.f;

    // A tile load: 128 rows x 8 k, one float4 per thread
    const int arow = tid >> 1;
    const int acol = (tid & 1) * 4;
    // B tile load: 8 k-rows x 128 n, one float4 per thread
    const int brow = tid >> 5;
    const int bcol = (tid & 31) * 4;

    const float* Aptr = g_Hall + (size_t)(bm + arow) * HID + acol;
    const float* Bptr = Wq + (size_t)brow * VOCAB + bn + bcol;

    for (int k0 = 0; k0 < HID; k0 += 8) {
        float4 av = *reinterpret_cast<const float4*>(Aptr + k0);
        float4 bv = *reinterpret_cast<const float4*>(Bptr + (size_t)k0 * VOCAB);
        As[acol + 0][arow] = av.x;
        As[acol + 1][arow] = av.y;
        As[acol + 2][arow] = av.z;
        As[acol + 3][arow] = av.w;
        *reinterpret_cast<float4*>(&Bs[brow][bcol]) = bv;
        __syncthreads();

        #pragma unroll
        for (int k = 0; k < 8; k++) {
            float a[8], bb[8];
            #pragma unroll
            for (int i = 0; i < 8; i++) a[i] = As[k][ty * 8 + i];
            #pragma unroll
            for (int jj = 0; jj < 8; jj++) bb[jj] = Bs[k][tx * 8 + jj];
            #pragma unroll
            for (int i = 0; i < 8; i++)
                #pragma unroll
                for (int jj = 0; jj < 8; jj++)
                    acc[i][jj] += a[i] * bb[jj];
        }
        __syncthreads();
    }

    #pragma unroll
    for (int i = 0; i < 8; i++) {
        const int row = bm + ty * 8 + i;
        #pragma unroll
        for (int jj = 0; jj < 8; jj += 4) {
            const int col = bn + tx * 8 + jj;
            float4 v;
            v.x = acc[i][jj + 0] + bq[col + 0];
            v.y = acc[i][jj + 1] + bq[col + 1];
            v.z = acc[i][jj + 2] + bq[col + 2];
            v.w = acc[i][jj + 3] + bq[col + 3];
            *reinterpret_cast<float4*>(&C[(size_t)row * VOCAB + col]) = v;
        }
    }
}

// Optional tail: H_final (B, HID) appended after outputs if harness expects it
__global__ void copy_hfinal(float* __restrict__ out)
{
    int i = blockIdx.x * 256 + threadIdx.x;
    if (i < B * HID)
        out[i] = g_Hall[(size_t)(T - 1) * B * HID + i];
}

extern "C" void kernel_launch(void* const* d_in, const int* in_sizes, int n_in,
                              void* d_out, int out_size)
{
    const int*   X     = (const int*)d_in[0];
    const float* state = (const float*)d_in[1];
    const float* W_xh  = (const float*)d_in[2];
    const float* W_hh  = (const float*)d_in[3];
    const float* b_h   = (const float*)d_in[4];
    const float* W_hq  = (const float*)d_in[5];
    const float* b_q   = (const float*)d_in[6];
    float* out = (float*)d_out;

    // 1) sequential recurrence: 512 dependent step kernels
    dim3 sgrid(8, 8);
    for (int t = 0; t < T; t++) {
        rnn_step<<<sgrid, 256>>>(X, state, W_xh, W_hh, b_h, t);
    }

    // 2) big batched projection GEMM
    dim3 ggrid(VOCAB / 128, M_TOT / 128);
    proj_gemm<<<ggrid, 256>>>(W_hq, b_q, out);

    // 3) H_final tail if the output buffer includes it
    if (out_size >= M_TOT * VOCAB + B * HID) {
        copy_hfinal<<<(B * HID + 255) / 256, 256>>>(out + (size_t)M_TOT * VOCAB);
    }
}

// round 3
// speedup vs baseline: 2.0812x; 2.0812x over previous
#include <cuda_runtime.h>
#include <math.h>

#define B 32
#define T 512
#define HID 512
#define VOCAB 4096
#define M_TOT (T * B)

// Persistent-recurrence tiling
#define NJT 16          // j-tiles (blockIdx.x), 32 j each
#define NG  8           // batch groups (blockIdx.y), 4 batches each
#define JW  32          // hidden cols per block
#define GB  4           // batches per group
#define WS_STRIDE 516   // padded row length for Ws[j][k]  (516*4 % 16 == 0, j-stride 4 banks)
#define SH_STRIDE 520   // padded row length for sH[b][k]  (b-stride 8 banks)

__device__ float g_Hall[T * B * HID];       // 32 MB scratch: all hidden states
__device__ unsigned g_cnt[NG];              // per-group monotonic barrier counters
__device__ unsigned g_exit[NG];             // per-group exit/reset counters

// ---------------------------------------------------------------------------
// Persistent recurrence: all 512 steps in ONE kernel.
// Grid (NJT, NG) = 128 blocks, 256 threads. Each block owns a 512x32 slice of
// W_hh cached in SMEM for the whole kernel. Per-group software barrier (16
// blocks) between steps; groups never sync with each other.
// ---------------------------------------------------------------------------
__global__ void __launch_bounds__(256) rnn_persist(
    const int* __restrict__ X,        // (B, T)
    const float* __restrict__ state,  // (B, HID)
    const float* __restrict__ W_xh,   // (VOCAB, HID)
    const float* __restrict__ W_hh,   // (HID, HID)
    const float* __restrict__ b_h)    // (HID)
{
    extern __shared__ float smem[];
    float* Ws   = smem;                                  // [JW][WS_STRIDE]
    float* sH   = Ws + JW * WS_STRIDE;                   // [GB][SH_STRIDE]
    float* sRed = sH + GB * SH_STRIDE;                   // [8][128]

    const int tid = threadIdx.x;
    const int jt  = blockIdx.x;         // j tile
    const int grp = blockIdx.y;         // batch group
    const int j0  = jt * JW;
    const int b0  = grp * GB;

    // ---- Preload W_hh slice: Ws[jr][k] = W_hh[k][j0+jr], once for all steps
    {
        const int lane8 = tid & 7;
        const int kk    = tid >> 3;     // 0..31
        for (int kb = 0; kb < HID; kb += 32) {
            const int k = kb + kk;
            float4 v = *reinterpret_cast<const float4*>(&W_hh[(size_t)k * HID + j0 + lane8 * 4]);
            Ws[(lane8 * 4 + 0) * WS_STRIDE + k] = v.x;
            Ws[(lane8 * 4 + 1) * WS_STRIDE + k] = v.y;
            Ws[(lane8 * 4 + 2) * WS_STRIDE + k] = v.z;
            Ws[(lane8 * 4 + 3) * WS_STRIDE + k] = v.w;
        }
    }

    // thread decomposition for the step GEMM:
    //   jq = tid&7   -> handles j = jq, jq+8, jq+16, jq+24 (relative)
    //   bb = (tid>>3)&3 -> one batch row
    //   ks = tid>>5  -> k slice [ks*64, ks*64+64)
    const int jq = tid & 7;
    const int bb = (tid >> 3) & 3;
    const int ks = tid >> 5;
    const int kbase = ks * 64;

    __syncthreads();

    for (int t = 0; t < T; t++) {
        // ---- load H_{t-1} rows for this group into smem (coalesced float4)
        const float* Hprev = (t == 0) ? state
                                      : (g_Hall + (size_t)(t - 1) * B * HID);
        for (int i = tid; i < GB * (HID / 4); i += 256) {
            const int bi  = i >> 7;            // i / 128
            const int kk4 = i & 127;
            float4 v = reinterpret_cast<const float4*>(&Hprev[(size_t)(b0 + bi) * HID])[kk4];
            *reinterpret_cast<float4*>(&sH[bi * SH_STRIDE + kk4 * 4]) = v;
        }
        __syncthreads();

        // ---- partial dot products: acc[i] = sum_k sH[bb][k] * Ws[jq+8i][k]
        float acc0 = 0.f, acc1 = 0.f, acc2 = 0.f, acc3 = 0.f;
        const float* hrow = &sH[bb * SH_STRIDE + kbase];
        const float* w0 = &Ws[(jq +  0) * WS_STRIDE + kbase];
        const float* w1 = &Ws[(jq +  8) * WS_STRIDE + kbase];
        const float* w2 = &Ws[(jq + 16) * WS_STRIDE + kbase];
        const float* w3 = &Ws[(jq + 24) * WS_STRIDE + kbase];
        #pragma unroll
        for (int kk = 0; kk < 64; kk += 4) {
            const float4 h = *reinterpret_cast<const float4*>(&hrow[kk]);
            const float4 a = *reinterpret_cast<const float4*>(&w0[kk]);
            const float4 b = *reinterpret_cast<const float4*>(&w1[kk]);
            const float4 c = *reinterpret_cast<const float4*>(&w2[kk]);
            const float4 d = *reinterpret_cast<const float4*>(&w3[kk]);
            acc0 += a.x * h.x + a.y * h.y + a.z * h.z + a.w * h.w;
            acc1 += b.x * h.x + b.y * h.y + b.z * h.z + b.w * h.w;
            acc2 += c.x * h.x + c.y * h.y + c.z * h.z + c.w * h.w;
            acc3 += d.x * h.x + d.y * h.y + d.z * h.z + d.w * h.w;
        }
        sRed[ks * 128 + bb * 32 + jq +  0] = acc0;
        sRed[ks * 128 + bb * 32 + jq +  8] = acc1;
        sRed[ks * 128 + bb * 32 + jq + 16] = acc2;
        sRed[ks * 128 + bb * 32 + jq + 24] = acc3;
        __syncthreads();

        // ---- finalize 128 outputs: k-reduce, add embed row + bias, tanh, store
        if (tid < 128) {
            float s = 0.f;
            #pragma unroll
            for (int q = 0; q < 8; q++) s += sRed[q * 128 + tid];
            const int bi = tid >> 5;          // 0..3
            const int jr = tid & 31;
            const int b  = b0 + bi;
            const int j  = j0 + jr;
            const int tok = X[b * T + t];
            s += __ldg(&W_xh[(size_t)tok * HID + j]) + __ldg(&b_h[j]);
            g_Hall[((size_t)t * B + b) * HID + j] = tanhf(s);
        }
        __syncthreads();

        // ---- per-group barrier across the 16 j-tile blocks
        if (tid == 0) {
            __threadfence();
            atomicAdd(&g_cnt[grp], 1u);
            const unsigned target = (unsigned)(NJT * (t + 1));
            unsigned v;
            do {
                asm volatile("ld.global.acquire.gpu.u32 %0, [%1];"
                             : "=r"(v) : "l"(&g_cnt[grp]));
            } while (v < target);
        }
        __syncthreads();
    }

    // ---- reset barrier state for the next graph replay (deterministic)
    if (tid == 0) {
        const unsigned v = atomicAdd(&g_exit[grp], 1u);
        if (v == NJT - 1) {
            g_cnt[grp]  = 0;
            g_exit[grp] = 0;
            __threadfence();
        }
    }
}

// ---------------------------------------------------------------------------
// Projection GEMM: C[M_TOT, VOCAB] = g_Hall @ W_hq + b_q
// 128x128 tile, BK=16, 256 threads, 8x8 register tile
// ---------------------------------------------------------------------------
__global__ void __launch_bounds__(256) proj_gemm(
    const float* __restrict__ Wq,     // (HID, VOCAB)
    const float* __restrict__ bq,     // (VOCAB)
    float* __restrict__ C)            // (M_TOT, VOCAB)
{
    __shared__ float As[16][128];
    __shared__ float Bs[16][132];

    const int tid = threadIdx.x;
    const int bm = blockIdx.y * 128;
    const int bn = blockIdx.x * 128;
    const int tx = tid & 15;
    const int ty = tid >> 4;

    float acc[8][8];
    #pragma unroll
    for (int i = 0; i < 8; i++)
        #pragma unroll
        for (int jj = 0; jj < 8; jj++) acc[i][jj] = 0.f;

    const int arow = tid >> 1;
    const int ac   = (tid & 1) * 8;
    const int brow = tid >> 5;             // 0..7 (+8 for second row)
    const int bcol = (tid & 31) * 4;

    const float* Aptr  = g_Hall + (size_t)(bm + arow) * HID + ac;
    const float* Bptr0 = Wq + (size_t)brow * VOCAB + bn + bcol;
    const float* Bptr1 = Bptr0 + (size_t)8 * VOCAB;

    for (int k0 = 0; k0 < HID; k0 += 16) {
        float4 a0 = *reinterpret_cast<const float4*>(Aptr + k0);
        float4 a1 = *reinterpret_cast<const float4*>(Aptr + k0 + 4);
        float4 v0 = *reinterpret_cast<const float4*>(Bptr0 + (size_t)k0 * VOCAB);
        float4 v1 = *reinterpret_cast<const float4*>(Bptr1 + (size_t)k0 * VOCAB);
        As[ac + 0][arow] = a0.x;  As[ac + 1][arow] = a0.y;
        As[ac + 2][arow] = a0.z;  As[ac + 3][arow] = a0.w;
        As[ac + 4][arow] = a1.x;  As[ac + 5][arow] = a1.y;
        As[ac + 6][arow] = a1.z;  As[ac + 7][arow] = a1.w;
        *reinterpret_cast<float4*>(&Bs[brow][bcol])     = v0;
        *reinterpret_cast<float4*>(&Bs[brow + 8][bcol]) = v1;
        __syncthreads();

        #pragma unroll
        for (int k = 0; k < 16; k++) {
            float a[8], bbv[8];
            #pragma unroll
            for (int i = 0; i < 8; i++) a[i] = As[k][ty * 8 + i];
            #pragma unroll
            for (int jj = 0; jj < 8; jj++) bbv[jj] = Bs[k][tx * 8 + jj];
            #pragma unroll
            for (int i = 0; i < 8; i++)
                #pragma unroll
                for (int jj = 0; jj < 8; jj++)
                    acc[i][jj] += a[i] * bbv[jj];
        }
        __syncthreads();
    }

    #pragma unroll
    for (int i = 0; i < 8; i++) {
        const int row = bm + ty * 8 + i;
        #pragma unroll
        for (int jj = 0; jj < 8; jj += 4) {
            const int col = bn + tx * 8 + jj;
            float4 v;
            v.x = acc[i][jj + 0] + bq[col + 0];
            v.y = acc[i][jj + 1] + bq[col + 1];
            v.z = acc[i][jj + 2] + bq[col + 2];
            v.w = acc[i][jj + 3] + bq[col + 3];
            *reinterpret_cast<float4*>(&C[(size_t)row * VOCAB + col]) = v;
        }
    }
}

__global__ void copy_hfinal(float* __restrict__ out)
{
    int i = blockIdx.x * 256 + threadIdx.x;
    if (i < B * HID)
        out[i] = g_Hall[(size_t)(T - 1) * B * HID + i];
}

extern "C" void kernel_launch(void* const* d_in, const int* in_sizes, int n_in,
                              void* d_out, int out_size)
{
    const int*   X     = (const int*)d_in[0];
    const float* state = (const float*)d_in[1];
    const float* W_xh  = (const float*)d_in[2];
    const float* W_hh  = (const float*)d_in[3];
    const float* b_h   = (const float*)d_in[4];
    const float* W_hq  = (const float*)d_in[5];
    const float* b_q   = (const float*)d_in[6];
    float* out = (float*)d_out;

    const int smem_bytes = (JW * WS_STRIDE + GB * SH_STRIDE + 8 * 128) * (int)sizeof(float);
    cudaFuncSetAttribute(rnn_persist, cudaFuncAttributeMaxDynamicSharedMemorySize, smem_bytes);

    // 1) whole recurrence in one persistent kernel (128 co-resident blocks)
    rnn_persist<<<dim3(NJT, NG), 256, smem_bytes>>>(X, state, W_xh, W_hh, b_h);

    // 2) batched projection GEMM
    dim3 ggrid(VOCAB / 128, M_TOT / 128);
    proj_gemm<<<ggrid, 256>>>(W_hq, b_q, out);

    // 3) H_final tail if the output buffer includes it
    if (out_size >= M_TOT * VOCAB + B * HID) {
        copy_hfinal<<<(B * HID + 255) / 256, 256>>>(out + (size_t)M_TOT * VOCAB);
    }
}

// round 7
// speedup vs baseline: 2.6581x; 1.2772x over previous
#include <cuda_runtime.h>
#include <cuda_bf16.h>
#include <math.h>
#include <stdint.h>

#define B 32
#define T 512
#define HID 512
#define VOCAB 4096
#define M_TOT (T * B)

// ---- recurrence tiling ----
#define NJT 16
#define NG  8
#define JW  32
#define GB  4
#define WS_STRIDE 516
#define SH_STRIDE 520

// ---- mma.sync projection GEMM config ----
#define PM 128
#define PN 128
#define PK 32
#define NCHUNK (HID / PK)        // 16
#define ASTRIDE 40               // padded row length (bf16 elems) -> 80B, conflict-free ldmatrix
#define TILE_BYTES 10240         // 128 * 40 * 2
#define OFF_AHI 0
#define OFF_ALO 10240
#define OFF_BHI 20480
#define OFF_BLO 30720
#define STAGE_BYTES 40960
#define PROJ_SMEM (2 * STAGE_BYTES)   // 80 KB

__device__ float         g_Hall[M_TOT * HID];     // 32 MB fp32 hidden states
__device__ __nv_bfloat16 g_Ahi[M_TOT * HID];      // 16 MB
__device__ __nv_bfloat16 g_Alo[M_TOT * HID];      // 16 MB
__device__ __nv_bfloat16 g_Bhi[VOCAB * HID];      // 4 MB  (W_hq^T hi, K-major)
__device__ __nv_bfloat16 g_Blo[VOCAB * HID];      // 4 MB
__device__ unsigned g_cnt[NG];
__device__ unsigned g_exit[NG];

// ============================================================================
// helpers
// ============================================================================
__device__ __forceinline__ uint32_t smem_u32(const void* p) {
    uint32_t a;
    asm("{ .reg .u64 t; cvta.to.shared.u64 t, %1; cvt.u32.u64 %0, t; }"
        : "=r"(a) : "l"(p));
    return a;
}

__device__ __forceinline__ void cp16(uint32_t dst, const void* src) {
    asm volatile("cp.async.cg.shared.global [%0], [%1], 16;"
                 :: "r"(dst), "l"(src) : "memory");
}

template <int N>
__device__ __forceinline__ void cp_wait() {
    asm volatile("cp.async.wait_group %0;" :: "n"(N) : "memory");
}

__device__ __forceinline__ void ldsm4(uint32_t* r, uint32_t addr) {
    asm volatile("ldmatrix.sync.aligned.m8n8.x4.shared.b16 {%0,%1,%2,%3}, [%4];"
                 : "=r"(r[0]), "=r"(r[1]), "=r"(r[2]), "=r"(r[3]) : "r"(addr));
}

__device__ __forceinline__ void mma_bf16(float* c, const uint32_t* a, const uint32_t* b) {
    asm volatile(
        "mma.sync.aligned.m16n8k16.row.col.f32.bf16.bf16.f32 "
        "{%0,%1,%2,%3}, {%4,%5,%6,%7}, {%8,%9}, {%0,%1,%2,%3};"
        : "+f"(c[0]), "+f"(c[1]), "+f"(c[2]), "+f"(c[3])
        : "r"(a[0]), "r"(a[1]), "r"(a[2]), "r"(a[3]), "r"(b[0]), "r"(b[1]));
}

// ============================================================================
// Persistent recurrence: 512 steps, per-group software barrier.
// Also emits bf16 hi/lo split of H for the tensor projection.
// ============================================================================
__global__ void __launch_bounds__(256) rnn_persist(
    const int* __restrict__ X,
    const float* __restrict__ state,
    const float* __restrict__ W_xh,
    const float* __restrict__ W_hh,
    const float* __restrict__ b_h)
{
    extern __shared__ float smem[];
    float* Ws   = smem;
    float* sH   = Ws + JW * WS_STRIDE;
    float* sRed = sH + GB * SH_STRIDE;

    const int tid = threadIdx.x;
    const int jt  = blockIdx.x;
    const int grp = blockIdx.y;
    const int j0  = jt * JW;
    const int b0  = grp * GB;

    {   // preload W_hh slice once (transposed into SMEM)
        const int lane8 = tid & 7;
        const int kk    = tid >> 3;
        for (int kb = 0; kb < HID; kb += 32) {
            const int k = kb + kk;
            float4 v = *reinterpret_cast<const float4*>(&W_hh[(size_t)k * HID + j0 + lane8 * 4]);
            Ws[(lane8 * 4 + 0) * WS_STRIDE + k] = v.x;
            Ws[(lane8 * 4 + 1) * WS_STRIDE + k] = v.y;
            Ws[(lane8 * 4 + 2) * WS_STRIDE + k] = v.z;
            Ws[(lane8 * 4 + 3) * WS_STRIDE + k] = v.w;
        }
    }

    const int jq = tid & 7;
    const int bb = (tid >> 3) & 3;
    const int ks = tid >> 5;
    const int kbase = ks * 64;

    int fb = -1, fj = -1;
    float bh_reg = 0.f;
    const int* xrow = 0;
    if (tid < 128) {
        fb = b0 + (tid >> 5);
        fj = j0 + (tid & 31);
        bh_reg = __ldg(&b_h[fj]);
        xrow = X + fb * T;
    }

    __syncthreads();

    for (int t = 0; t < T; t++) {
        float eb = 0.f;
        if (tid < 128) {
            const int tok = __ldg(&xrow[t]);
            eb = __ldg(&W_xh[(size_t)tok * HID + fj]) + bh_reg;
        }

        const float* Hprev = (t == 0) ? state : (g_Hall + (size_t)(t - 1) * B * HID);
        for (int i = tid; i < GB * (HID / 4); i += 256) {
            const int bi  = i >> 7;
            const int kk4 = i & 127;
            float4 v = reinterpret_cast<const float4*>(&Hprev[(size_t)(b0 + bi) * HID])[kk4];
            *reinterpret_cast<float4*>(&sH[bi * SH_STRIDE + kk4 * 4]) = v;
        }
        __syncthreads();

        float acc0 = 0.f, acc1 = 0.f, acc2 = 0.f, acc3 = 0.f;
        const float* hrow = &sH[bb * SH_STRIDE + kbase];
        const float* w0 = &Ws[(jq +  0) * WS_STRIDE + kbase];
        const float* w1 = &Ws[(jq +  8) * WS_STRIDE + kbase];
        const float* w2 = &Ws[(jq + 16) * WS_STRIDE + kbase];
        const float* w3 = &Ws[(jq + 24) * WS_STRIDE + kbase];
        #pragma unroll
        for (int kk = 0; kk < 64; kk += 4) {
            const float4 h = *reinterpret_cast<const float4*>(&hrow[kk]);
            const float4 a = *reinterpret_cast<const float4*>(&w0[kk]);
            const float4 b = *reinterpret_cast<const float4*>(&w1[kk]);
            const float4 c = *reinterpret_cast<const float4*>(&w2[kk]);
            const float4 d = *reinterpret_cast<const float4*>(&w3[kk]);
            acc0 += a.x * h.x + a.y * h.y + a.z * h.z + a.w * h.w;
            acc1 += b.x * h.x + b.y * h.y + b.z * h.z + b.w * h.w;
            acc2 += c.x * h.x + c.y * h.y + c.z * h.z + c.w * h.w;
            acc3 += d.x * h.x + d.y * h.y + d.z * h.z + d.w * h.w;
        }
        sRed[ks * 128 + bb * 32 + jq +  0] = acc0;
        sRed[ks * 128 + bb * 32 + jq +  8] = acc1;
        sRed[ks * 128 + bb * 32 + jq + 16] = acc2;
        sRed[ks * 128 + bb * 32 + jq + 24] = acc3;
        __syncthreads();

        if (tid < 128) {
            float s = 0.f;
            #pragma unroll
            for (int q = 0; q < 8; q++) s += sRed[q * 128 + tid];
            s += eb;
            const float h = tanhf(s);
            const size_t ridx = ((size_t)t * B + fb) * HID + fj;
            g_Hall[ridx] = h;
            const __nv_bfloat16 hi = __float2bfloat16(h);
            g_Ahi[ridx] = hi;
            g_Alo[ridx] = __float2bfloat16(h - __bfloat162float(hi));
        }
        __syncthreads();

        if (tid == 0) {
            asm volatile("red.release.gpu.global.add.u32 [%0], %1;"
                         :: "l"(&g_cnt[grp]), "r"(1u) : "memory");
            const unsigned target = (unsigned)(NJT * (t + 1));
            unsigned v;
            do {
                asm volatile("ld.global.acquire.gpu.u32 %0, [%1];"
                             : "=r"(v) : "l"(&g_cnt[grp]));
            } while (v < target);
        }
        __syncthreads();
    }

    if (tid == 0) {
        const unsigned v = atomicAdd(&g_exit[grp], 1u);
        if (v == NJT - 1) {
            g_cnt[grp]  = 0;
            g_exit[grp] = 0;
            __threadfence();
        }
    }
}

// ============================================================================
// Prep: transpose + split W_hq (HID, VOCAB) -> Bhi/Blo (VOCAB, HID) bf16
// ============================================================================
__global__ void __launch_bounds__(256) prep_b(const float* __restrict__ Wq)
{
    __shared__ float tl[32][33];
    const int n0 = blockIdx.x * 32;
    const int k0 = blockIdx.y * 32;
    const int tx = threadIdx.x;
    const int ty = threadIdx.y;

    #pragma unroll
    for (int i = 0; i < 32; i += 8)
        tl[ty + i][tx] = Wq[(size_t)(k0 + ty + i) * VOCAB + n0 + tx];
    __syncthreads();

    #pragma unroll
    for (int i = 0; i < 32; i += 8) {
        const float v = tl[tx][ty + i];
        const size_t o = (size_t)(n0 + ty + i) * HID + k0 + tx;
        const __nv_bfloat16 hi = __float2bfloat16(v);
        g_Bhi[o] = hi;
        g_Blo[o] = __float2bfloat16(v - __bfloat162float(hi));
    }
}

// ============================================================================
// Projection GEMM on mma.sync.m16n8k16 bf16 (3-pass hi/lo split)
// CTA 128x128, BK=32, double-buffered cp.async, 8 warps of 64x32.
// ============================================================================
__device__ __forceinline__ void load_chunk(
    uint32_t dstbase, int tid, int c,
    const __nv_bfloat16* aH, const __nv_bfloat16* aL,
    const __nv_bfloat16* bH, const __nv_bfloat16* bL)
{
    const int r = tid >> 1;          // 0..127 (A row / B row)
    const int h = tid & 1;           // k half (16 elems)
    const uint32_t d = dstbase + (uint32_t)(r * 80 + h * 32);
    const size_t g = (size_t)r * HID + c * PK + h * 16;
    cp16(d + OFF_AHI,      aH + g);
    cp16(d + OFF_AHI + 16, aH + g + 8);
    cp16(d + OFF_ALO,      aL + g);
    cp16(d + OFF_ALO + 16, aL + g + 8);
    cp16(d + OFF_BHI,      bH + g);
    cp16(d + OFF_BHI + 16, bH + g + 8);
    cp16(d + OFF_BLO,      bL + g);
    cp16(d + OFF_BLO + 16, bL + g + 8);
    asm volatile("cp.async.commit_group;" ::: "memory");
}

__global__ void __launch_bounds__(256) proj_mma(
    const float* __restrict__ bq,
    float* __restrict__ C)
{
    extern __shared__ char smc[];
    const uint32_t sb = smem_u32(smc);
    const int tid  = threadIdx.x;
    const int lane = tid & 31;
    const int wid  = tid >> 5;
    const int wm   = wid & 1;        // 0..1 -> 64-row half
    const int wn   = wid >> 1;       // 0..3 -> 32-col quarter
    const int bm = blockIdx.y * PM;
    const int bn = blockIdx.x * PN;

    const __nv_bfloat16* aH = g_Ahi + (size_t)bm * HID;
    const __nv_bfloat16* aL = g_Alo + (size_t)bm * HID;
    const __nv_bfloat16* bH = g_Bhi + (size_t)bn * HID;
    const __nv_bfloat16* bL = g_Blo + (size_t)bn * HID;

    float acc[4][4][4];
    #pragma unroll
    for (int i = 0; i < 4; i++)
        #pragma unroll
        for (int j = 0; j < 4; j++)
            #pragma unroll
            for (int q = 0; q < 4; q++) acc[i][j][q] = 0.f;

    // precomputed ldmatrix shared addresses (byte offsets within a stage)
    const uint32_t a_off = (uint32_t)(((wm * 64 + (lane & 15)) * ASTRIDE
                                       + ((lane >> 4) << 3)) * 2);
    const uint32_t b_off = (uint32_t)(((wn * 32 + (lane & 7) + (((lane >> 4) & 1) << 3)) * ASTRIDE
                                       + (((lane >> 3) & 1) << 3)) * 2);

    load_chunk(sb, tid, 0, aH, aL, bH, bL);

    for (int c = 0; c < NCHUNK; c++) {
        if (c + 1 < NCHUNK) {
            load_chunk(sb + (uint32_t)((c + 1) & 1) * STAGE_BYTES, tid, c + 1, aH, aL, bH, bL);
            cp_wait<1>();
        } else {
            cp_wait<0>();
        }
        __syncthreads();

        const uint32_t stage = sb + (uint32_t)(c & 1) * STAGE_BYTES;
        #pragma unroll
        for (int ksi = 0; ksi < 2; ksi++) {
            const uint32_t kadd = (uint32_t)(ksi * 32);   // 16 elems * 2B
            uint32_t ah[4][4], al[4][4];
            #pragma unroll
            for (int mf = 0; mf < 4; mf++) {
                const uint32_t o = stage + a_off + kadd + (uint32_t)(mf * 16 * ASTRIDE * 2);
                ldsm4(ah[mf], o + OFF_AHI);
                ldsm4(al[mf], o + OFF_ALO);
            }
            uint32_t bh2[2][4], bl2[2][4];
            #pragma unroll
            for (int nf2 = 0; nf2 < 2; nf2++) {
                const uint32_t o = stage + b_off + kadd + (uint32_t)(nf2 * 16 * ASTRIDE * 2);
                ldsm4(bh2[nf2], o + OFF_BHI);
                ldsm4(bl2[nf2], o + OFF_BLO);
            }
            #pragma unroll
            for (int mf = 0; mf < 4; mf++) {
                #pragma unroll
                for (int nf = 0; nf < 4; nf++) {
                    const uint32_t* bhp = &bh2[nf >> 1][(nf & 1) * 2];
                    const uint32_t* blp = &bl2[nf >> 1][(nf & 1) * 2];
                    mma_bf16(acc[mf][nf], ah[mf], bhp);   // hi*hi
                    mma_bf16(acc[mf][nf], al[mf], bhp);   // lo*hi
                    mma_bf16(acc[mf][nf], ah[mf], blp);   // hi*lo
                }
            }
        }
        __syncthreads();
    }

    // epilogue: direct stores with bias
    #pragma unroll
    for (int mf = 0; mf < 4; mf++) {
        const int row0 = bm + wm * 64 + mf * 16 + (lane >> 2);
        #pragma unroll
        for (int nf = 0; nf < 4; nf++) {
            const int col = bn + wn * 32 + nf * 8 + ((lane & 3) << 1);
            const float2 bias = *reinterpret_cast<const float2*>(bq + col);
            float2 v0, v1;
            v0.x = acc[mf][nf][0] + bias.x;
            v0.y = acc[mf][nf][1] + bias.y;
            v1.x = acc[mf][nf][2] + bias.x;
            v1.y = acc[mf][nf][3] + bias.y;
            *reinterpret_cast<float2*>(&C[(size_t)row0 * VOCAB + col]) = v0;
            *reinterpret_cast<float2*>(&C[(size_t)(row0 + 8) * VOCAB + col]) = v1;
        }
    }
}

__global__ void copy_hfinal(float* __restrict__ out)
{
    int i = blockIdx.x * 256 + threadIdx.x;
    if (i < B * HID)
        out[i] = g_Hall[(size_t)(T - 1) * B * HID + i];
}

// ============================================================================
extern "C" void kernel_launch(void* const* d_in, const int* in_sizes, int n_in,
                              void* d_out, int out_size)
{
    const int*   X     = (const int*)d_in[0];
    const float* state = (const float*)d_in[1];
    const float* W_xh  = (const float*)d_in[2];
    const float* W_hh  = (const float*)d_in[3];
    const float* b_h   = (const float*)d_in[4];
    const float* W_hq  = (const float*)d_in[5];
    const float* b_q   = (const float*)d_in[6];
    float* out = (float*)d_out;

    // 0) split/transpose W_hq -> bf16 hi/lo
    prep_b<<<dim3(VOCAB / 32, HID / 32), dim3(32, 8)>>>(W_hq);

    // 1) persistent recurrence (also emits bf16 hi/lo of H)
    const int rec_smem = (JW * WS_STRIDE + GB * SH_STRIDE + 8 * 128) * (int)sizeof(float);
    cudaFuncSetAttribute(rnn_persist, cudaFuncAttributeMaxDynamicSharedMemorySize, rec_smem);
    rnn_persist<<<dim3(NJT, NG), 256, rec_smem>>>(X, state, W_xh, W_hh, b_h);

    // 2) tensor-core (mma.sync) projection GEMM
    cudaFuncSetAttribute(proj_mma, cudaFuncAttributeMaxDynamicSharedMemorySize, PROJ_SMEM);
    proj_mma<<<dim3(VOCAB / PN, M_TOT / PM), 256, PROJ_SMEM>>>(b_q, out);

    // 3) optional H_final tail
    if (out_size >= M_TOT * VOCAB + B * HID) {
        copy_hfinal<<<(B * HID + 255) / 256, 256>>>(out + (size_t)M_TOT * VOCAB);
    }
}